// round 1
// baseline (speedup 1.0000x reference)
#include <cuda_runtime.h>

// Problem constants (fixed by the reference: B=4, C=8, H=W=1024, R=1 cross kernel, wrap pad)
constexpr int Hh = 1024;
constexpr int Ww = 1024;
constexpr int PLANE = Hh * Ww;          // 1,048,576
constexpr int W4 = Ww / 4;              // 256 float4 per row

// Accurate fp32 exp (Cody-Waite reduction + cephes degree-6 poly, ~1 ulp).
// Immune to -use_fast_math rewriting of expf; only FMAs + one int bit-trick scale.
__device__ __forceinline__ float exp_acc(float x) {
    // clamp keeps the 2^n bit-trick in range; comparisons vs rand in [0,1) are unaffected
    x = fminf(fmaxf(x, -87.3f), 88.0f);
    float n = rintf(x * 1.44269504088896341f);
    float r = fmaf(n, -0.693359375f, x);        // Cody-Waite hi
    r = fmaf(n, 2.12194440e-4f, r);             // Cody-Waite lo
    float rr = r * r;
    float y = 1.9875691500e-4f;
    y = fmaf(y, r, 1.3981999507e-3f);
    y = fmaf(y, r, 8.3334519073e-3f);
    y = fmaf(y, r, 4.1665795894e-2f);
    y = fmaf(y, r, 1.6666665459e-1f);
    y = fmaf(y, r, 5.0000001201e-1f);
    y = fmaf(y, rr, r);
    y = y + 1.0f;
    float sc = __int_as_float(((int)n + 127) << 23);
    return y * sc;
}

__device__ __forceinline__ float flip_one(float s, float J, float bf, float r, bool drop) {
    float de = 2.0f * s * J;
    bool flip;
    if (de <= 0.0f) {
        flip = drop;                            // p = 1, rand < 1 always true
    } else {
        float p = exp_acc(-de * bf);
        flip = (r < p) && drop;
    }
    return flip ? -s : s;
}

__global__ __launch_bounds__(256) void ising_step_kernel(
    const float* __restrict__ x,      // (4, 9, 1024, 1024): s = ch 0..7, b = ch 8
    const float* __restrict__ rnd,    // (4, 8, 1024, 1024)
    const float* __restrict__ drop,   // (1024, 1024)
    float* __restrict__ out)          // (4, 9, 1024, 1024)
{
    int tid = blockIdx.x * blockDim.x + threadIdx.x;   // 0 .. 4*1024*256-1
    int w4 = tid & (W4 - 1);
    int h  = (tid >> 8) & (Hh - 1);
    int b  = tid >> 18;
    int w  = w4 * 4;

    const float* xb = x + b * 9 * PLANE;
    int rowc = h * Ww;
    int rowu = ((h + Hh - 1) & (Hh - 1)) * Ww;   // wrap up
    int rowd = ((h + 1) & (Hh - 1)) * Ww;        // wrap down
    int wl = (w + Ww - 1) & (Ww - 1);            // wrap left of lane 0
    int wr = (w + 4) & (Ww - 1);                 // wrap right of lane 3

    // Pass 1: accumulate J (channel-summed cross-neighbor sum) and cache centers.
    float4 J = make_float4(0.f, 0.f, 0.f, 0.f);
    float4 cen[8];
    #pragma unroll
    for (int c = 0; c < 8; c++) {
        const float* sp = xb + c * PLANE;
        float4 cc = *reinterpret_cast<const float4*>(sp + rowc + w);
        float4 up = *reinterpret_cast<const float4*>(sp + rowu + w);
        float4 dn = *reinterpret_cast<const float4*>(sp + rowd + w);
        float lf = sp[rowc + wl];
        float rt = sp[rowc + wr];
        cen[c] = cc;
        J.x += (up.x + dn.x) + (lf   + cc.y);
        J.y += (up.y + dn.y) + (cc.x + cc.z);
        J.z += (up.z + dn.z) + (cc.y + cc.w);
        J.w += (up.w + dn.w) + (cc.z + rt);
    }

    // Field b and dropout mask for these 4 pixels
    float4 bf = *reinterpret_cast<const float4*>(xb + 8 * PLANE + rowc + w);
    float4 dr = *reinterpret_cast<const float4*>(drop + rowc + w);
    bool d0 = dr.x > 0.5f, d1 = dr.y > 0.5f, d2 = dr.z > 0.5f, d3 = dr.w > 0.5f;

    float* ob = out + b * 9 * PLANE;
    // Pass-through channel 8 (the field)
    *reinterpret_cast<float4*>(ob + 8 * PLANE + rowc + w) = bf;

    const float* rb = rnd + b * 8 * PLANE;
    #pragma unroll
    for (int c = 0; c < 8; c++) {
        float4 rv = *reinterpret_cast<const float4*>(rb + c * PLANE + rowc + w);
        float4 o;
        o.x = flip_one(cen[c].x, J.x, bf.x, rv.x, d0);
        o.y = flip_one(cen[c].y, J.y, bf.y, rv.y, d1);
        o.z = flip_one(cen[c].z, J.z, bf.z, rv.z, d2);
        o.w = flip_one(cen[c].w, J.w, bf.w, rv.w, d3);
        *reinterpret_cast<float4*>(ob + c * PLANE + rowc + w) = o;
    }
}

extern "C" void kernel_launch(void* const* d_in, const int* in_sizes, int n_in,
                              void* d_out, int out_size) {
    const float* x    = (const float*)d_in[0];   // (4,9,1024,1024)
    const float* rnd  = (const float*)d_in[1];   // (4,8,1024,1024)
    const float* drop = (const float*)d_in[2];   // (1024,1024)
    // d_in[3] = nn_kernel: fixed cross structure, baked into the kernel
    float* out = (float*)d_out;

    int total_threads = 4 * Hh * W4;             // 1,048,576
    int block = 256;
    int grid = total_threads / block;            // 4096
    ising_step_kernel<<<grid, block>>>(x, rnd, drop, out);
}

// round 2
// speedup vs baseline: 1.6486x; 1.6486x over previous
#include <cuda_runtime.h>

// Problem constants (fixed by the reference: B=4, C=8, H=W=1024, R=1 cross kernel, wrap pad)
constexpr int Hh = 1024;
constexpr int Ww = 1024;
constexpr int PLANE = Hh * Ww;          // 1,048,576
constexpr int W4 = Ww / 4;              // 256 float4 per row

// Accurate fp32 exp (Cody-Waite reduction + cephes degree-6 poly, ~1 ulp).
// Immune to -use_fast_math rewriting of expf; only FMAs + one int bit-trick scale.
__device__ __forceinline__ float exp_acc(float x) {
    x = fminf(fmaxf(x, -87.3f), 88.0f);
    float n = rintf(x * 1.44269504088896341f);
    float r = fmaf(n, -0.693359375f, x);        // Cody-Waite hi
    r = fmaf(n, 2.12194440e-4f, r);             // Cody-Waite lo
    float rr = r * r;
    float y = 1.9875691500e-4f;
    y = fmaf(y, r, 1.3981999507e-3f);
    y = fmaf(y, r, 8.3334519073e-3f);
    y = fmaf(y, r, 4.1665795894e-2f);
    y = fmaf(y, r, 1.6666665459e-1f);
    y = fmaf(y, r, 5.0000001201e-1f);
    y = fmaf(y, rr, r);
    y = y + 1.0f;
    float sc = __int_as_float(((int)n + 127) << 23);
    return y * sc;
}

__device__ __forceinline__ float flip_one(float s, float J, float bf, float r, bool drop) {
    float de = 2.0f * s * J;
    bool flip;
    if (de <= 0.0f) {
        flip = drop;                            // p = 1, rand in [0,1) < 1 always
    } else {
        float p = exp_acc(-de * bf);
        flip = (r < p) && drop;
    }
    return flip ? -s : s;
}

__device__ __forceinline__ float4 ld_cs4(const float* p) {
    return __ldcs(reinterpret_cast<const float4*>(p));
}

__global__ __launch_bounds__(256, 6) void ising_step_kernel(
    const float* __restrict__ x,      // (4, 9, 1024, 1024): s = ch 0..7, b = ch 8
    const float* __restrict__ rnd,    // (4, 8, 1024, 1024)
    const float* __restrict__ drop,   // (1024, 1024)
    float* __restrict__ out)          // (4, 9, 1024, 1024)
{
    int tid = blockIdx.x * blockDim.x + threadIdx.x;   // 0 .. 4*1024*256-1
    int w4 = tid & (W4 - 1);
    int h  = (tid >> 8) & (Hh - 1);
    int b  = tid >> 18;
    int w  = w4 * 4;

    const float* xb = x + b * 9 * PLANE;
    int rowc = h * Ww;
    int rowu = ((h + Hh - 1) & (Hh - 1)) * Ww;   // wrap up
    int rowd = ((h + 1) & (Hh - 1)) * Ww;        // wrap down
    int wl = (w + Ww - 1) & (Ww - 1);            // wrap left of lane 0
    int wr = (w + 4) & (Ww - 1);                 // wrap right of lane 3

    // Pass 1: accumulate J (channel-summed cross-neighbor sum). Centers are
    // NOT cached in registers — pass 2 re-loads them (L1 hit) to keep regs low.
    float4 J = make_float4(0.f, 0.f, 0.f, 0.f);
    #pragma unroll
    for (int c = 0; c < 8; c++) {
        const float* sp = xb + c * PLANE;
        float4 cc = *reinterpret_cast<const float4*>(sp + rowc + w);  // cached (reused in pass 2)
        float4 up = ld_cs4(sp + rowu + w);       // streaming: read-once in this thread
        float4 dn = ld_cs4(sp + rowd + w);
        float lf = sp[rowc + wl];
        float rt = sp[rowc + wr];
        J.x += (up.x + dn.x) + (lf   + cc.y);
        J.y += (up.y + dn.y) + (cc.x + cc.z);
        J.z += (up.z + dn.z) + (cc.y + cc.w);
        J.w += (up.w + dn.w) + (cc.z + rt);
    }

    // Field b and dropout mask for these 4 pixels
    float4 bf = *reinterpret_cast<const float4*>(xb + 8 * PLANE + rowc + w);
    float4 dr = *reinterpret_cast<const float4*>(drop + rowc + w);
    bool d0 = dr.x > 0.5f, d1 = dr.y > 0.5f, d2 = dr.z > 0.5f, d3 = dr.w > 0.5f;

    float* ob = out + b * 9 * PLANE;
    // Pass-through channel 8 (the field)
    *reinterpret_cast<float4*>(ob + 8 * PLANE + rowc + w) = bf;

    const float* rb = rnd + b * 8 * PLANE;
    #pragma unroll
    for (int c = 0; c < 8; c++) {
        const float* sp = xb + c * PLANE;
        float4 cc = *reinterpret_cast<const float4*>(sp + rowc + w);  // L1 hit (loaded in pass 1)
        float4 rv = ld_cs4(rb + c * PLANE + rowc + w);                // read-once stream
        float4 o;
        o.x = flip_one(cc.x, J.x, bf.x, rv.x, d0);
        o.y = flip_one(cc.y, J.y, bf.y, rv.y, d1);
        o.z = flip_one(cc.z, J.z, bf.z, rv.z, d2);
        o.w = flip_one(cc.w, J.w, bf.w, rv.w, d3);
        *reinterpret_cast<float4*>(ob + c * PLANE + rowc + w) = o;
    }
}

extern "C" void kernel_launch(void* const* d_in, const int* in_sizes, int n_in,
                              void* d_out, int out_size) {
    const float* x    = (const float*)d_in[0];   // (4,9,1024,1024)
    const float* rnd  = (const float*)d_in[1];   // (4,8,1024,1024)
    const float* drop = (const float*)d_in[2];   // (1024,1024)
    // d_in[3] = nn_kernel: fixed cross structure, baked into the kernel
    float* out = (float*)d_out;

    int total_threads = 4 * Hh * W4;             // 1,048,576
    int block = 256;
    int grid = total_threads / block;            // 4096
    ising_step_kernel<<<grid, block>>>(x, rnd, drop, out);
}